// round 1
// baseline (speedup 1.0000x reference)
#include <cuda_runtime.h>

// Problem constants (fixed shapes for this problem)
#define NN 100000   // nodes
#define EE 1000000  // edges
#define RR 1000     // relations
#define DD 100      // feature dim
#define D4 25       // DD / 4 (float4 chunks)

// ---------------- device scratch (static; no allocations allowed) ----------
__device__ int    g_row_ptr[NN + 1];
__device__ float4 g_rel_norm[RR * D4];      // normalized relation embeddings
__device__ float  g_rw[4][RR];              // r_hat . w_n  for c = enc*2+layer
__device__ float  g_rr[4][RR];              // r_hat . w_r
__device__ float4 g_bufE0[NN * D4];         // ent-encoder feats, layer-parity 0
__device__ float4 g_bufE1[NN * D4];
__device__ float4 g_bufR0[NN * D4];         // rel-encoder feats
__device__ float4 g_bufR1[NN * D4];
__device__ float  g_ndotE[2][NN];           // feats . w_n per node, per layer parity
__device__ float  g_ndotR[2][NN];

// ---------------------------------------------------------------------------
__device__ __forceinline__ void wred2(float& a, float& b) {
#pragma unroll
    for (int o = 16; o; o >>= 1) {
        a += __shfl_xor_sync(0xffffffffu, a, o);
        b += __shfl_xor_sync(0xffffffffu, b, o);
    }
}
__device__ __forceinline__ float dot4(float4 a, float4 b) {
    return a.x * b.x + a.y * b.y + a.z * b.z + a.w * b.w;
}

// ---------------- K0: row_ptr from sorted dst ------------------------------
__global__ void k_rowptr(const int* __restrict__ dst) {
    int n = blockIdx.x * blockDim.x + threadIdx.x;
    if (n > NN) return;
    int lo = 0, hi = EE;
    while (lo < hi) {
        int mid = (lo + hi) >> 1;
        if (dst[mid] < n) lo = mid + 1; else hi = mid;
    }
    g_row_ptr[n] = lo;
}

// ---------------- K1: relation normalization + per-relation scalars --------
__global__ void k_rel(const float* __restrict__ rel_emb,
                      const float* __restrict__ attn_e,
                      const float* __restrict__ attn_r) {
    int warp = (blockIdx.x * blockDim.x + threadIdx.x) >> 5;
    int lane = threadIdx.x & 31;
    if (warp >= RR) return;

    float4 v = {0.f, 0.f, 0.f, 0.f};
    if (lane < D4) v = reinterpret_cast<const float4*>(rel_emb)[warp * D4 + lane];
    float ss = dot4(v, v), dummy = 0.f;
    wred2(ss, dummy);
    float inv = 1.f / fmaxf(sqrtf(ss), 1e-12f);
    v.x *= inv; v.y *= inv; v.z *= inv; v.w *= inv;
    if (lane < D4) g_rel_norm[warp * D4 + lane] = v;

#pragma unroll
    for (int c = 0; c < 4; c++) {
        const float* attn = (c < 2 ? attn_e : attn_r) + (c & 1) * (3 * DD);
        float4 wn = {0.f, 0.f, 0.f, 0.f}, wr = {0.f, 0.f, 0.f, 0.f};
        if (lane < D4) {
            wn = reinterpret_cast<const float4*>(attn + DD)[lane];
            wr = reinterpret_cast<const float4*>(attn + 2 * DD)[lane];
        }
        float dn = dot4(v, wn);
        float dr = dot4(v, wr);
        wred2(dn, dr);
        if (lane == 0) { g_rw[c][warp] = dn; g_rr[c][warp] = dr; }
    }
}

// ---------------- K2: initial segment means + tanh + n_dot(layer 0) --------
__global__ void __launch_bounds__(256)
k_init(const float* __restrict__ ent_emb,
       const float* __restrict__ rel_emb,
       const int* __restrict__ src,
       const int* __restrict__ erel,
       const float* __restrict__ attn_e,
       const float* __restrict__ attn_r,
       float* __restrict__ out) {
    int warp = (blockIdx.x * blockDim.x + threadIdx.x) >> 5;
    int lane = threadIdx.x & 31;
    if (warp >= NN) return;
    int beg = g_row_ptr[warp], end = g_row_ptr[warp + 1];

    const float4* ent4 = reinterpret_cast<const float4*>(ent_emb);
    const float4* rel4 = reinterpret_cast<const float4*>(rel_emb);
    float4 aE = {0.f, 0.f, 0.f, 0.f}, aR = {0.f, 0.f, 0.f, 0.f};
    for (int e = beg; e < end; e++) {
        int s = src[e], r = erel[e];
        if (lane < D4) {
            float4 fe = ent4[s * D4 + lane];
            float4 fr = rel4[r * D4 + lane];
            aE.x += fe.x; aE.y += fe.y; aE.z += fe.z; aE.w += fe.w;
            aR.x += fr.x; aR.y += fr.y; aR.z += fr.z; aR.w += fr.w;
        }
    }
    float inv = 1.f / (float)max(end - beg, 1);
    float4 fE, fR;
    fE.x = tanhf(aE.x * inv); fE.y = tanhf(aE.y * inv);
    fE.z = tanhf(aE.z * inv); fE.w = tanhf(aE.w * inv);
    fR.x = tanhf(aR.x * inv); fR.y = tanhf(aR.y * inv);
    fR.z = tanhf(aR.z * inv); fR.w = tanhf(aR.w * inv);

    float4* out4 = reinterpret_cast<float4*>(out);
    if (lane < D4) {
        g_bufE0[warp * D4 + lane] = fE;
        g_bufR0[warp * D4 + lane] = fR;
        out4[warp * 150 + lane]      = fE;  // ent cols [0,100)
        out4[warp * 150 + 75 + lane] = fR;  // rel cols [300,400)
    }

    // n_dot for layer 0 (w_n = attn[0:DD offset DD])
    float4 wnE = {0.f, 0.f, 0.f, 0.f}, wnR = {0.f, 0.f, 0.f, 0.f};
    if (lane < D4) {
        wnE = reinterpret_cast<const float4*>(attn_e + DD)[lane];
        wnR = reinterpret_cast<const float4*>(attn_r + DD)[lane];
    }
    float dE = dot4(fE, wnE);
    float dR = dot4(fR, wnR);
    wred2(dE, dR);
    if (lane == 0) { g_ndotE[0][warp] = dE; g_ndotR[0][warp] = dR; }
}

// ---------------- K3: one attention layer, both encoders fused -------------
template <int LAYER>
__global__ void __launch_bounds__(256)
k_layer(const int* __restrict__ src,
        const int* __restrict__ erel,
        const float* __restrict__ attn_e,
        const float* __restrict__ attn_r,
        float* __restrict__ out) {
    int warp = (blockIdx.x * blockDim.x + threadIdx.x) >> 5;
    int lane = threadIdx.x & 31;
    if (warp >= NN) return;
    int beg = g_row_ptr[warp], end = g_row_ptr[warp + 1];

    const float4* curE = (LAYER == 0) ? g_bufE0 : g_bufE1;
    const float4* curR = (LAYER == 0) ? g_bufR0 : g_bufR1;
    const float* ndE = g_ndotE[LAYER];
    const float* ndR = g_ndotR[LAYER];
    const float* rwE = g_rw[LAYER];
    const float* rrE = g_rr[LAYER];
    const float* rwR = g_rw[2 + LAYER];
    const float* rrR = g_rr[2 + LAYER];

    float mE = -1e30f, ZE = 0.f;
    float mR = -1e30f, ZR = 0.f;
    float4 accE = {0.f, 0.f, 0.f, 0.f};
    float4 accR = {0.f, 0.f, 0.f, 0.f};

    for (int e = beg; e < end; e++) {
        int s = src[e], r = erel[e];
        float4 fE = {0.f, 0.f, 0.f, 0.f}, fR = {0.f, 0.f, 0.f, 0.f},
               rv = {0.f, 0.f, 0.f, 0.f};
        if (lane < D4) {
            fE = curE[s * D4 + lane];
            fR = curR[s * D4 + lane];
            rv = g_rel_norm[r * D4 + lane];
        }
        float pE = dot4(fE, rv);
        float pR = dot4(fR, rv);
        wred2(pE, pR);  // broadcast dot products to all lanes

        // logit (self-term dropped: constant within softmax segment)
        float lE = ndE[s] - 2.f * pE * rwE[r] + rrE[r];
        float lR = ndR[s] - 2.f * pR * rwR[r] + rrR[r];

        // online softmax, encoder E
        {
            float mn = fmaxf(mE, lE);
            float sc = __expf(mE - mn);
            float w  = __expf(lE - mn);
            ZE = ZE * sc + w;
            float b = 2.f * w * pE;
            accE.x = accE.x * sc + w * fE.x - b * rv.x;
            accE.y = accE.y * sc + w * fE.y - b * rv.y;
            accE.z = accE.z * sc + w * fE.z - b * rv.z;
            accE.w = accE.w * sc + w * fE.w - b * rv.w;
            mE = mn;
        }
        // online softmax, encoder R
        {
            float mn = fmaxf(mR, lR);
            float sc = __expf(mR - mn);
            float w  = __expf(lR - mn);
            ZR = ZR * sc + w;
            float b = 2.f * w * pR;
            accR.x = accR.x * sc + w * fR.x - b * rv.x;
            accR.y = accR.y * sc + w * fR.y - b * rv.y;
            accR.z = accR.z * sc + w * fR.z - b * rv.z;
            accR.w = accR.w * sc + w * fR.w - b * rv.w;
            mR = mn;
        }
    }

    float4 oE = {0.f, 0.f, 0.f, 0.f}, oR = {0.f, 0.f, 0.f, 0.f};
    if (end > beg) {
        float izE = 1.f / ZE, izR = 1.f / ZR;
        oE.x = tanhf(accE.x * izE); oE.y = tanhf(accE.y * izE);
        oE.z = tanhf(accE.z * izE); oE.w = tanhf(accE.w * izE);
        oR.x = tanhf(accR.x * izR); oR.y = tanhf(accR.y * izR);
        oR.z = tanhf(accR.z * izR); oR.w = tanhf(accR.w * izR);
    }

    float4* out4 = reinterpret_cast<float4*>(out);
    if (lane < D4) {
        out4[warp * 150 + (LAYER + 1) * D4 + lane]      = oE;
        out4[warp * 150 + 75 + (LAYER + 1) * D4 + lane] = oR;
        if (LAYER == 0) {
            g_bufE1[warp * D4 + lane] = oE;
            g_bufR1[warp * D4 + lane] = oR;
        }
    }

    if (LAYER == 0) {
        // n_dot for layer 1
        float4 wnE = {0.f, 0.f, 0.f, 0.f}, wnR = {0.f, 0.f, 0.f, 0.f};
        if (lane < D4) {
            wnE = reinterpret_cast<const float4*>(attn_e + 3 * DD + DD)[lane];
            wnR = reinterpret_cast<const float4*>(attn_r + 3 * DD + DD)[lane];
        }
        float dE = dot4(oE, wnE);
        float dR = dot4(oR, wnR);
        wred2(dE, dR);
        if (lane == 0) { g_ndotE[1][warp] = dE; g_ndotR[1][warp] = dR; }
    }
}

// ---------------------------------------------------------------------------
extern "C" void kernel_launch(void* const* d_in, const int* in_sizes, int n_in,
                              void* d_out, int out_size) {
    const float* ent_emb = (const float*)d_in[0];
    const float* rel_emb = (const float*)d_in[1];
    const float* attn_e  = (const float*)d_in[2];
    const float* attn_r  = (const float*)d_in[3];
    const int*   src     = (const int*)d_in[4];
    const int*   dst     = (const int*)d_in[5];
    const int*   erel    = (const int*)d_in[6];
    float* out = (float*)d_out;

    k_rowptr<<<(NN + 1 + 255) / 256, 256>>>(dst);
    k_rel<<<(RR * 32 + 255) / 256, 256>>>(rel_emb, attn_e, attn_r);
    k_init<<<(NN * 32) / 256, 256>>>(ent_emb, rel_emb, src, erel,
                                     attn_e, attn_r, out);
    k_layer<0><<<(NN * 32) / 256, 256>>>(src, erel, attn_e, attn_r, out);
    k_layer<1><<<(NN * 32) / 256, 256>>>(src, erel, attn_e, attn_r, out);
}

// round 2
// speedup vs baseline: 1.2533x; 1.2533x over previous
#include <cuda_runtime.h>

#define NN 100000   // nodes
#define EE 1000000  // edges
#define RR 1000     // relations
#define DD 100      // feature dim
#define D4 25       // DD / 4

// ---------------- device scratch (static; no allocations) ------------------
__device__ int    g_row_ptr[NN + 1];
__device__ float4 g_rel_norm[RR * D4];       // normalized relation embeddings
__device__ float4 g_relsc[2][RR];            // (rwE, rrE, rwR, rrR) per layer
__device__ float2 g_nd[2][NN];               // (ndotE, ndotR) per layer parity
__device__ float4 g_feat0[NN * 50];          // interleaved: [n*50+l]=E, [n*50+25+l]=R
__device__ float4 g_feat1[NN * 50];

// ---------------------------------------------------------------------------
__device__ __forceinline__ void wred2(float& a, float& b) {
#pragma unroll
    for (int o = 16; o; o >>= 1) {
        a += __shfl_xor_sync(0xffffffffu, a, o);
        b += __shfl_xor_sync(0xffffffffu, b, o);
    }
}
__device__ __forceinline__ void wred4(float& a, float& b, float& c, float& d) {
#pragma unroll
    for (int o = 16; o; o >>= 1) {
        a += __shfl_xor_sync(0xffffffffu, a, o);
        b += __shfl_xor_sync(0xffffffffu, b, o);
        c += __shfl_xor_sync(0xffffffffu, c, o);
        d += __shfl_xor_sync(0xffffffffu, d, o);
    }
}
__device__ __forceinline__ float dot4(float4 a, float4 b) {
    return a.x * b.x + a.y * b.y + a.z * b.z + a.w * b.w;
}

// ---------------- K0: row_ptr from sorted dst ------------------------------
__global__ void k_rowptr(const int* __restrict__ dst) {
    int n = blockIdx.x * blockDim.x + threadIdx.x;
    if (n > NN) return;
    int lo = 0, hi = EE;
    while (lo < hi) {
        int mid = (lo + hi) >> 1;
        if (dst[mid] < n) lo = mid + 1; else hi = mid;
    }
    g_row_ptr[n] = lo;
}

// ---------------- K1: relation normalization + per-relation scalars --------
__global__ void k_rel(const float* __restrict__ rel_emb,
                      const float* __restrict__ attn_e,
                      const float* __restrict__ attn_r) {
    int warp = (blockIdx.x * blockDim.x + threadIdx.x) >> 5;
    int lane = threadIdx.x & 31;
    if (warp >= RR) return;

    float4 v = {0.f, 0.f, 0.f, 0.f};
    if (lane < D4) v = reinterpret_cast<const float4*>(rel_emb)[warp * D4 + lane];
    float ss = dot4(v, v), dummy = 0.f;
    wred2(ss, dummy);
    float inv = 1.f / fmaxf(sqrtf(ss), 1e-12f);
    v.x *= inv; v.y *= inv; v.z *= inv; v.w *= inv;
    if (lane < D4) g_rel_norm[warp * D4 + lane] = v;

#pragma unroll
    for (int c = 0; c < 4; c++) {   // c = enc*2 + layer
        const float* attn = (c < 2 ? attn_e : attn_r) + (c & 1) * (3 * DD);
        float4 wn = {0.f, 0.f, 0.f, 0.f}, wr = {0.f, 0.f, 0.f, 0.f};
        if (lane < D4) {
            wn = reinterpret_cast<const float4*>(attn + DD)[lane];
            wr = reinterpret_cast<const float4*>(attn + 2 * DD)[lane];
        }
        float dn = dot4(v, wn);
        float dr = dot4(v, wr);
        wred2(dn, dr);
        if (lane == 0) {
            int layer = c & 1;
            if (c < 2) { g_relsc[layer][warp].x = dn; g_relsc[layer][warp].y = dr; }
            else       { g_relsc[layer][warp].z = dn; g_relsc[layer][warp].w = dr; }
        }
    }
}

// ---------------- K2: initial segment means + tanh + ndot(layer 0) ---------
__global__ void __launch_bounds__(256)
k_init(const float* __restrict__ ent_emb,
       const float* __restrict__ rel_emb,
       const int* __restrict__ src,
       const int* __restrict__ erel,
       const float* __restrict__ attn_e,
       const float* __restrict__ attn_r,
       float* __restrict__ out) {
    int warp = (blockIdx.x * blockDim.x + threadIdx.x) >> 5;
    int lane = threadIdx.x & 31;
    if (warp >= NN) return;
    int beg = g_row_ptr[warp], end = g_row_ptr[warp + 1];

    const float4* ent4 = reinterpret_cast<const float4*>(ent_emb);
    const float4* rel4 = reinterpret_cast<const float4*>(rel_emb);
    float4 aE = {0.f, 0.f, 0.f, 0.f}, aR = {0.f, 0.f, 0.f, 0.f};
    int e = beg;
    for (; e + 1 < end; e += 2) {
        int s0 = src[e], r0 = erel[e];
        int s1 = src[e + 1], r1 = erel[e + 1];
        if (lane < D4) {
            float4 fe0 = ent4[s0 * D4 + lane];
            float4 fr0 = rel4[r0 * D4 + lane];
            float4 fe1 = ent4[s1 * D4 + lane];
            float4 fr1 = rel4[r1 * D4 + lane];
            aE.x += fe0.x + fe1.x; aE.y += fe0.y + fe1.y;
            aE.z += fe0.z + fe1.z; aE.w += fe0.w + fe1.w;
            aR.x += fr0.x + fr1.x; aR.y += fr0.y + fr1.y;
            aR.z += fr0.z + fr1.z; aR.w += fr0.w + fr1.w;
        }
    }
    if (e < end) {
        int s0 = src[e], r0 = erel[e];
        if (lane < D4) {
            float4 fe0 = ent4[s0 * D4 + lane];
            float4 fr0 = rel4[r0 * D4 + lane];
            aE.x += fe0.x; aE.y += fe0.y; aE.z += fe0.z; aE.w += fe0.w;
            aR.x += fr0.x; aR.y += fr0.y; aR.z += fr0.z; aR.w += fr0.w;
        }
    }
    float inv = 1.f / (float)max(end - beg, 1);
    float4 fE, fR;
    fE.x = tanhf(aE.x * inv); fE.y = tanhf(aE.y * inv);
    fE.z = tanhf(aE.z * inv); fE.w = tanhf(aE.w * inv);
    fR.x = tanhf(aR.x * inv); fR.y = tanhf(aR.y * inv);
    fR.z = tanhf(aR.z * inv); fR.w = tanhf(aR.w * inv);

    float4* out4 = reinterpret_cast<float4*>(out);
    if (lane < D4) {
        g_feat0[warp * 50 + lane]      = fE;
        g_feat0[warp * 50 + 25 + lane] = fR;
        out4[warp * 150 + lane]      = fE;   // ent layer-0 block
        out4[warp * 150 + 75 + lane] = fR;   // rel layer-0 block
    }

    float4 wnE = {0.f, 0.f, 0.f, 0.f}, wnR = {0.f, 0.f, 0.f, 0.f};
    if (lane < D4) {
        wnE = reinterpret_cast<const float4*>(attn_e + DD)[lane];
        wnR = reinterpret_cast<const float4*>(attn_r + DD)[lane];
    }
    float dE = dot4(fE, wnE);
    float dR = dot4(fR, wnR);
    wred2(dE, dR);
    if (lane == 0) g_nd[0][warp] = make_float2(dE, dR);
}

// ---------------- K3: one attention layer, both encoders, unroll-2 --------
template <int LAYER>
__global__ void __launch_bounds__(256)
k_layer(const int* __restrict__ src,
        const int* __restrict__ erel,
        const float* __restrict__ attn_e,
        const float* __restrict__ attn_r,
        float* __restrict__ out) {
    int warp = (blockIdx.x * blockDim.x + threadIdx.x) >> 5;
    int lane = threadIdx.x & 31;
    if (warp >= NN) return;
    int beg = g_row_ptr[warp], end = g_row_ptr[warp + 1];

    const float4* __restrict__ feat = (LAYER == 0) ? g_feat0 : g_feat1;
    const float2* __restrict__ nd   = g_nd[LAYER];
    const float4* __restrict__ rsc  = g_relsc[LAYER];

    float ZE = 0.f, ZR = 0.f;
    float4 accE = {0.f, 0.f, 0.f, 0.f};
    float4 accR = {0.f, 0.f, 0.f, 0.f};
    bool act = lane < D4;

    int e = beg;
    for (; e + 1 < end; e += 2) {
        int s0 = src[e],     r0 = erel[e];
        int s1 = src[e + 1], r1 = erel[e + 1];
        float4 fE0 = {0,0,0,0}, fR0 = {0,0,0,0}, rv0 = {0,0,0,0};
        float4 fE1 = {0,0,0,0}, fR1 = {0,0,0,0}, rv1 = {0,0,0,0};
        if (act) {
            fE0 = feat[s0 * 50 + lane];
            fR0 = feat[s0 * 50 + 25 + lane];
            rv0 = g_rel_norm[r0 * D4 + lane];
            fE1 = feat[s1 * 50 + lane];
            fR1 = feat[s1 * 50 + 25 + lane];
            rv1 = g_rel_norm[r1 * D4 + lane];
        }
        float2 nd0 = nd[s0], nd1 = nd[s1];
        float4 sc0 = rsc[r0], sc1 = rsc[r1];

        float pE0 = dot4(fE0, rv0), pR0 = dot4(fR0, rv0);
        float pE1 = dot4(fE1, rv1), pR1 = dot4(fR1, rv1);
        wred4(pE0, pR0, pE1, pR1);

        float wE0 = __expf(nd0.x - 2.f * pE0 * sc0.x + sc0.y);
        float wR0 = __expf(nd0.y - 2.f * pR0 * sc0.z + sc0.w);
        float wE1 = __expf(nd1.x - 2.f * pE1 * sc1.x + sc1.y);
        float wR1 = __expf(nd1.y - 2.f * pR1 * sc1.z + sc1.w);
        ZE += wE0 + wE1;
        ZR += wR0 + wR1;

        float bE0 = 2.f * wE0 * pE0, bR0 = 2.f * wR0 * pR0;
        float bE1 = 2.f * wE1 * pE1, bR1 = 2.f * wR1 * pR1;
        accE.x += wE0 * fE0.x - bE0 * rv0.x + wE1 * fE1.x - bE1 * rv1.x;
        accE.y += wE0 * fE0.y - bE0 * rv0.y + wE1 * fE1.y - bE1 * rv1.y;
        accE.z += wE0 * fE0.z - bE0 * rv0.z + wE1 * fE1.z - bE1 * rv1.z;
        accE.w += wE0 * fE0.w - bE0 * rv0.w + wE1 * fE1.w - bE1 * rv1.w;
        accR.x += wR0 * fR0.x - bR0 * rv0.x + wR1 * fR1.x - bR1 * rv1.x;
        accR.y += wR0 * fR0.y - bR0 * rv0.y + wR1 * fR1.y - bR1 * rv1.y;
        accR.z += wR0 * fR0.z - bR0 * rv0.z + wR1 * fR1.z - bR1 * rv1.z;
        accR.w += wR0 * fR0.w - bR0 * rv0.w + wR1 * fR1.w - bR1 * rv1.w;
    }
    if (e < end) {
        int s0 = src[e], r0 = erel[e];
        float4 fE0 = {0,0,0,0}, fR0 = {0,0,0,0}, rv0 = {0,0,0,0};
        if (act) {
            fE0 = feat[s0 * 50 + lane];
            fR0 = feat[s0 * 50 + 25 + lane];
            rv0 = g_rel_norm[r0 * D4 + lane];
        }
        float2 nd0 = nd[s0];
        float4 sc0 = rsc[r0];
        float pE0 = dot4(fE0, rv0), pR0 = dot4(fR0, rv0);
        wred2(pE0, pR0);
        float wE0 = __expf(nd0.x - 2.f * pE0 * sc0.x + sc0.y);
        float wR0 = __expf(nd0.y - 2.f * pR0 * sc0.z + sc0.w);
        ZE += wE0; ZR += wR0;
        float bE0 = 2.f * wE0 * pE0, bR0 = 2.f * wR0 * pR0;
        accE.x += wE0 * fE0.x - bE0 * rv0.x;
        accE.y += wE0 * fE0.y - bE0 * rv0.y;
        accE.z += wE0 * fE0.z - bE0 * rv0.z;
        accE.w += wE0 * fE0.w - bE0 * rv0.w;
        accR.x += wR0 * fR0.x - bR0 * rv0.x;
        accR.y += wR0 * fR0.y - bR0 * rv0.y;
        accR.z += wR0 * fR0.z - bR0 * rv0.z;
        accR.w += wR0 * fR0.w - bR0 * rv0.w;
    }

    float4 oE = {0,0,0,0}, oR = {0,0,0,0};
    if (end > beg) {
        float izE = 1.f / ZE, izR = 1.f / ZR;
        oE.x = tanhf(accE.x * izE); oE.y = tanhf(accE.y * izE);
        oE.z = tanhf(accE.z * izE); oE.w = tanhf(accE.w * izE);
        oR.x = tanhf(accR.x * izR); oR.y = tanhf(accR.y * izR);
        oR.z = tanhf(accR.z * izR); oR.w = tanhf(accR.w * izR);
    }

    float4* out4 = reinterpret_cast<float4*>(out);
    if (act) {
        out4[warp * 150 + (LAYER + 1) * D4 + lane]      = oE;
        out4[warp * 150 + 75 + (LAYER + 1) * D4 + lane] = oR;
        if (LAYER == 0) {
            g_feat1[warp * 50 + lane]      = oE;
            g_feat1[warp * 50 + 25 + lane] = oR;
        }
    }

    if (LAYER == 0) {
        float4 wnE = {0,0,0,0}, wnR = {0,0,0,0};
        if (act) {
            wnE = reinterpret_cast<const float4*>(attn_e + 3 * DD + DD)[lane];
            wnR = reinterpret_cast<const float4*>(attn_r + 3 * DD + DD)[lane];
        }
        float dE = dot4(oE, wnE);
        float dR = dot4(oR, wnR);
        wred2(dE, dR);
        if (lane == 0) g_nd[1][warp] = make_float2(dE, dR);
    }
}

// ---------------------------------------------------------------------------
extern "C" void kernel_launch(void* const* d_in, const int* in_sizes, int n_in,
                              void* d_out, int out_size) {
    const float* ent_emb = (const float*)d_in[0];
    const float* rel_emb = (const float*)d_in[1];
    const float* attn_e  = (const float*)d_in[2];
    const float* attn_r  = (const float*)d_in[3];
    const int*   src     = (const int*)d_in[4];
    const int*   dst     = (const int*)d_in[5];
    const int*   erel    = (const int*)d_in[6];
    float* out = (float*)d_out;

    k_rowptr<<<(NN + 1 + 255) / 256, 256>>>(dst);
    k_rel<<<(RR * 32 + 255) / 256, 256>>>(rel_emb, attn_e, attn_r);
    k_init<<<(NN * 32) / 256, 256>>>(ent_emb, rel_emb, src, erel,
                                     attn_e, attn_r, out);
    k_layer<0><<<(NN * 32) / 256, 256>>>(src, erel, attn_e, attn_r, out);
    k_layer<1><<<(NN * 32) / 256, 256>>>(src, erel, attn_e, attn_r, out);
}